// round 12
// baseline (speedup 1.0000x reference)
#include <cuda_runtime.h>
#include <cuda_fp16.h>
#include <cstdint>

// Problem constants
#define Bb   8
#define Lseq 8192
#define Hd   768
#define Mtot (Bb * Lseq)        // 65536
#define LAMK 0.1f

// GEMM tiling: CTA 128M x 128 a-cols (+128 g-cols), f16 accumulate
#define KT    24                // K chunks of 32
#define RSB   80                // smem row stride bytes -> conflict-free ldmatrix
#define ATILE 10240             // 128 rows * 80B
#define BTILE 20480             // 256 rows * 80B (a rows then g rows)
#define STG   (ATILE + BTILE)   // 30720
#define NSTG  3
#define GSM   (NSTG * STG)      // 92160 bytes -> 2 CTAs/SM

// ---------------- scratch ----------------------------------------------------
__device__ __half g_vh[(size_t)Mtot * Hd];      // silu(x*D + conv) in fp16
__device__ __half g_wh[2 * Hd * Hd];            // W in fp16 (1536 x 768)
__device__ int    g_tap_idx[Hd * Lseq];
__device__ float  g_tap_val[Hd * Lseq];
__device__ int    g_tap_cnt[Hd];

// ---------------- helpers ----------------------------------------------------
__device__ __forceinline__ float sigmoidf_(float z) {
    return 1.0f / (1.0f + __expf(-z));
}

__device__ __forceinline__ uint32_t s2u(const void* p) {
    uint32_t a;
    asm("{ .reg .u64 t; cvta.to.shared.u64 t, %1; cvt.u32.u64 %0, t; }"
        : "=r"(a) : "l"(p));
    return a;
}

__device__ __forceinline__ void cp16(uint32_t dst, const void* src) {
    asm volatile("cp.async.cg.shared.global [%0], [%1], 16;\n"
                 :: "r"(dst), "l"(src));
}

__device__ __forceinline__ void ldsm4(uint32_t* r, uint32_t addr) {
    asm volatile("ldmatrix.sync.aligned.m8n8.x4.shared.b16 {%0,%1,%2,%3}, [%4];"
                 : "=r"(r[0]), "=r"(r[1]), "=r"(r[2]), "=r"(r[3]) : "r"(addr));
}

// fp16-accumulate mma: D,C are 2 regs of f16x2 (row r: c0,c1 | row r+8: c2,c3)
__device__ __forceinline__ void mma16816h(uint32_t* d, const uint32_t* a,
                                          uint32_t b0, uint32_t b1) {
    asm volatile(
        "mma.sync.aligned.m16n8k16.row.col.f16.f16.f16.f16 "
        "{%0,%1}, {%2,%3,%4,%5}, {%6,%7}, {%0,%1};\n"
        : "+r"(d[0]), "+r"(d[1])
        : "r"(a[0]), "r"(a[1]), "r"(a[2]), "r"(a[3]), "r"(b0), "r"(b1));
}

// ---------------- kernel 0: W fp32 -> fp16 -----------------------------------
__global__ void wconv_kernel(const float* __restrict__ W) {
    int i = blockIdx.x * 256 + threadIdx.x;
    g_wh[i] = __float2half_rn(W[i]);
}

// ---------------- kernel 1: soft-threshold + ordered tap compaction ----------
__global__ void build_taps_kernel(const float* __restrict__ kern) {
    int h = blockIdx.x * 8 + (threadIdx.x >> 5);
    int lane = threadIdx.x & 31;
    const float* kr = kern + (size_t)h * Lseq;
    int* ti = g_tap_idx + (size_t)h * Lseq;
    float* tv = g_tap_val + (size_t)h * Lseq;
    int cnt = 0;
    for (int base = 0; base < Lseq; base += 32) {
        float kv = kr[base + lane];
        float mag = fabsf(kv) - LAMK;
        bool p = mag > 0.0f;
        unsigned msk = __ballot_sync(0xffffffffu, p);
        if (p) {
            int pos = cnt + __popc(msk & ((1u << lane) - 1u));
            ti[pos] = base + lane;
            tv[pos] = copysignf(mag, kv);
        }
        cnt += __popc(msk);
    }
    if (lane == 0) g_tap_cnt[h] = cnt;
}

// ---------------- kernel 2: v = silu(x*D + sparse_causal_conv) -> fp16 -------
__global__ void prep_v_kernel(const float* __restrict__ x, const float* __restrict__ D) {
    const int H4 = Hd / 4;
    int i = blockIdx.x * blockDim.x + threadIdx.x;
    int m = i / H4;
    int h4 = (i - m * H4) * 4;

    float4 xv = *reinterpret_cast<const float4*>(x + (size_t)m * Hd + h4);
    float4 dv = *reinterpret_cast<const float4*>(D + h4);
    float s[4] = { xv.x * dv.x, xv.y * dv.y, xv.z * dv.z, xv.w * dv.w };

#pragma unroll
    for (int c = 0; c < 4; ++c) {
        int h = h4 + c;
        int cnt = g_tap_cnt[h];
        if (cnt > 0) {                         // cold path (taps survive threshold)
            int l = m & (Lseq - 1);
            int b = m >> 13;
            const int* ti = g_tap_idx + (size_t)h * Lseq;
            const float* tv = g_tap_val + (size_t)h * Lseq;
            float acc = 0.0f;
            for (int t = 0; t < cnt; ++t) {
                int j = ti[t];
                if (j <= l)
                    acc += tv[t] * x[((size_t)b * Lseq + (l - j)) * Hd + h];
            }
            s[c] += acc;
        }
    }

    __half2 h01 = __floats2half2_rn(s[0] * sigmoidf_(s[0]), s[1] * sigmoidf_(s[1]));
    __half2 h23 = __floats2half2_rn(s[2] * sigmoidf_(s[2]), s[3] * sigmoidf_(s[3]));
    uint2 pk;
    pk.x = *reinterpret_cast<uint32_t*>(&h01);
    pk.y = *reinterpret_cast<uint32_t*>(&h23);
    *reinterpret_cast<uint2*>(g_vh + (size_t)m * Hd + h4) = pk;
}

// ---------------- kernel 3: fp16 mma GEMM (f16 acc) + bias + GLU + residual --
// CTA: 128 M-rows x 128 a-cols (+128 g-cols). B smem rows 0..127 = W row n0+r,
// rows 128..255 = W row 768+n0+r. Warp grid 2(M) x 4(N): warp = 64M x 32a+32g.
__global__ void __launch_bounds__(256, 2)
gemm_fp16_kernel(const float* __restrict__ bias, const float* __restrict__ x,
                 float* __restrict__ out) {
    extern __shared__ char dsm[];
    uint32_t sb = s2u(dsm);
    const int tid  = threadIdx.x;
    const int lane = tid & 31;
    const int warp = tid >> 5;
    const int wm = warp >> 2;            // 0..1 -> 64 M-rows each
    const int wn = warp & 3;             // 0..3 -> 32 a-cols (+32 g-cols) each
    const int m0 = blockIdx.y * 128;
    const int n0 = blockIdx.x * 128;

    // loader mapping: 1536 16B units/stage (A:512, B:1024), 6 per thread
    uint32_t sdst[6];
    const __half* gsrc[6];
#pragma unroll
    for (int j = 0; j < 6; ++j) {
        int u = tid + j * 256;
        if (u < 512) {                         // A unit
            int row = u >> 2, q = u & 3;
            sdst[j] = (uint32_t)(row * RSB + q * 16);
            gsrc[j] = g_vh + (size_t)(m0 + row) * Hd + q * 8;
        } else {                               // B unit
            int bu = u - 512;
            int row = bu >> 2, q = bu & 3;
            int wrow = (row < 128) ? (n0 + row) : (640 + n0 + row);  // 768+n0+(row-128)
            sdst[j] = (uint32_t)(ATILE + row * RSB + q * 16);
            gsrc[j] = g_wh + (size_t)wrow * Hd + q * 8;
        }
    }

    // prologue: stages 0..1
#pragma unroll
    for (int s = 0; s < 2; ++s) {
        uint32_t st = sb + s * STG;
#pragma unroll
        for (int j = 0; j < 6; ++j)
            cp16(st + sdst[j], gsrc[j] + s * 32);
        asm volatile("cp.async.commit_group;" ::: "memory");
    }

    // ldmatrix per-lane offsets
    const int lro = (lane & 7) + ((lane >> 3) & 1) * 8;
    const int lu  = lane >> 4;
    uint32_t aoff[4], boffA[2], boffG[2];
#pragma unroll
    for (int mi = 0; mi < 4; ++mi)
        aoff[mi] = (uint32_t)((wm * 64 + mi * 16 + lro) * RSB + lu * 16);
#pragma unroll
    for (int hh = 0; hh < 2; ++hh) {
        boffA[hh] = (uint32_t)(ATILE + (wn * 32 + hh * 16 + lro) * RSB + lu * 16);
        boffG[hh] = (uint32_t)(ATILE + (128 + wn * 32 + hh * 16 + lro) * RSB + lu * 16);
    }

    uint32_t accA[4][4][2], accG[4][4][2];    // f16x2 accumulators
#pragma unroll
    for (int mi = 0; mi < 4; ++mi)
#pragma unroll
        for (int nj = 0; nj < 4; ++nj)
#pragma unroll
            for (int r = 0; r < 2; ++r) { accA[mi][nj][r] = 0u; accG[mi][nj][r] = 0u; }

    for (int t = 0; t < KT; ++t) {
        asm volatile("cp.async.wait_group 1;" ::: "memory");
        __syncthreads();

        if (t + 2 < KT) {
            uint32_t st = sb + ((t + 2) % NSTG) * STG;
            int kw = (t + 2) * 32;
#pragma unroll
            for (int j = 0; j < 6; ++j)
                cp16(st + sdst[j], gsrc[j] + kw);
        }
        asm volatile("cp.async.commit_group;" ::: "memory");

        uint32_t bbase = sb + (t % NSTG) * STG;
#pragma unroll
        for (int ks = 0; ks < 2; ++ks) {
            uint32_t kadd = (uint32_t)(ks * 32);   // 16 halves = 32B
            uint32_t afr[4][4];
#pragma unroll
            for (int mi = 0; mi < 4; ++mi)
                ldsm4(afr[mi], bbase + aoff[mi] + kadd);
            uint32_t ba[2][4], bg[2][4];
#pragma unroll
            for (int hh = 0; hh < 2; ++hh) {
                ldsm4(ba[hh], bbase + boffA[hh] + kadd);
                ldsm4(bg[hh], bbase + boffG[hh] + kadd);
            }
#pragma unroll
            for (int mi = 0; mi < 4; ++mi)
#pragma unroll
                for (int hh = 0; hh < 2; ++hh) {
                    mma16816h(accA[mi][2 * hh + 0], afr[mi], ba[hh][0], ba[hh][2]);
                    mma16816h(accA[mi][2 * hh + 1], afr[mi], ba[hh][1], ba[hh][3]);
                    mma16816h(accG[mi][2 * hh + 0], afr[mi], bg[hh][0], bg[hh][2]);
                    mma16816h(accG[mi][2 * hh + 1], afr[mi], bg[hh][1], bg[hh][3]);
                }
        }
    }

    // epilogue: unpack f16 accs, bias + GLU + residual
    const int r  = lane >> 2;
    const int c2 = (lane & 3) * 2;
#pragma unroll
    for (int nj = 0; nj < 4; ++nj) {
        int col = n0 + wn * 32 + ((nj >> 1) * 16) + (nj & 1) * 8 + c2;
        float ba0 = __ldg(bias + col),      ba1 = __ldg(bias + col + 1);
        float bg0 = __ldg(bias + Hd + col), bg1 = __ldg(bias + Hd + col + 1);
#pragma unroll
        for (int mi = 0; mi < 4; ++mi) {
            int mrow = m0 + wm * 64 + mi * 16 + r;
            {
                __half2 ah = *reinterpret_cast<__half2*>(&accA[mi][nj][0]);
                __half2 gh = *reinterpret_cast<__half2*>(&accG[mi][nj][0]);
                float a0 = __low2float(ah) + ba0, a1 = __high2float(ah) + ba1;
                float g0 = __low2float(gh) + bg0, g1 = __high2float(gh) + bg1;
                float2 xv = __ldg(reinterpret_cast<const float2*>(x + (size_t)mrow * Hd + col));
                float2 o;
                o.x = a0 * sigmoidf_(g0) + xv.x;
                o.y = a1 * sigmoidf_(g1) + xv.y;
                *reinterpret_cast<float2*>(out + (size_t)mrow * Hd + col) = o;
            }
            {
                int mr2 = mrow + 8;
                __half2 ah = *reinterpret_cast<__half2*>(&accA[mi][nj][1]);
                __half2 gh = *reinterpret_cast<__half2*>(&accG[mi][nj][1]);
                float a0 = __low2float(ah) + ba0, a1 = __high2float(ah) + ba1;
                float g0 = __low2float(gh) + bg0, g1 = __high2float(gh) + bg1;
                float2 xv = __ldg(reinterpret_cast<const float2*>(x + (size_t)mr2 * Hd + col));
                float2 o;
                o.x = a0 * sigmoidf_(g0) + xv.x;
                o.y = a1 * sigmoidf_(g1) + xv.y;
                *reinterpret_cast<float2*>(out + (size_t)mr2 * Hd + col) = o;
            }
        }
    }
}

// ---------------- launch ------------------------------------------------------
extern "C" void kernel_launch(void* const* d_in, const int* in_sizes, int n_in,
                              void* d_out, int out_size) {
    const float* x    = (const float*)d_in[0];   // (8, 8192, 768)
    const float* kern = (const float*)d_in[1];   // (1, 768, 8192)
    const float* D    = (const float*)d_in[2];   // (1, 768)
    const float* W    = (const float*)d_in[3];   // (1536, 768)
    const float* bias = (const float*)d_in[4];   // (1536,)
    float* out = (float*)d_out;                  // (8, 8192, 768)

    cudaFuncSetAttribute(gemm_fp16_kernel,
                         cudaFuncAttributeMaxDynamicSharedMemorySize, GSM);

    wconv_kernel<<<(2 * Hd * Hd) / 256, 256>>>(W);
    build_taps_kernel<<<Hd / 8, 256>>>(kern);

    int tot4 = Mtot * (Hd / 4);
    prep_v_kernel<<<tot4 / 256, 256>>>(x, D);

    dim3 grid(Hd / 128, Mtot / 128);             // (6, 512)
    gemm_fp16_kernel<<<grid, 256, GSM>>>(bias, x, out);
}